// round 5
// baseline (speedup 1.0000x reference)
#include <cuda_runtime.h>
#include <cstdint>

#define NSESS    4096
#define NTRIALS  2048
#define NWORDS   (NTRIALS / 32)        // 64 packed words per session

// filter chunking
#define FCHUNK   128                   // output trials per warp
#define FNCHUNK  (NTRIALS / FCHUNK)    // 16 chunks
#define FWARM    64                    // warmup trials (0.8^64 ~ 6e-7 contraction)

// packed bits: bit i of packed[w*NSESS+s] = (chose_left==outcome) at trial w*32+i
__device__ uint32_t g_packed[NWORDS * NSESS];

// ---------------------------------------------------------------------------
// Kernel 1: pack. One warp per QUARTER-session (512 trials); 4 fully-unrolled
// iters x 3 float4 loads = 12 LDG.128 batched per warp; 16384 warps
// -> ~1.8 MB in flight, enough to saturate DRAM read BW.
// ---------------------------------------------------------------------------
__global__ void __launch_bounds__(128)
pack_kernel(const float* __restrict__ in, uint32_t* __restrict__ packed) {
    const int lane  = threadIdx.x & 31;
    const int gwarp = blockIdx.x * 4 + (threadIdx.x >> 5);
    const int s     = gwarp >> 2;
    const int quart = gwarp & 3;

    const float* srow = in + (long)s * (NTRIALS * 3) + quart * (512 * 3);

#pragma unroll
    for (int it = 0; it < 4; it++) {
        const float4* p = (const float4*)(srow + it * 384) + 3 * lane;
        float4 x0 = p[0];   // cl0 cr0 o0  cl1
        float4 x1 = p[1];   // cr1 o1  cl2 cr2
        float4 x2 = p[2];   // o2  cl3 cr3 o3

        int b0 = (x0.x == x0.z);
        int b1 = (x0.w == x1.y);
        int b2 = (x1.z == x2.x);
        int b3 = (x2.y == x2.w);
        uint32_t nib = (uint32_t)(b0 | (b1 << 1) | (b2 << 2) | (b3 << 3));
        uint32_t v = nib << ((lane & 7) * 4);
        v |= __shfl_xor_sync(0xFFFFFFFFu, v, 1);
        v |= __shfl_xor_sync(0xFFFFFFFFu, v, 2);
        v |= __shfl_xor_sync(0xFFFFFFFFu, v, 4);
        if ((lane & 7) == 0) {
            int w = quart * 16 + it * 4 + (lane >> 3);
            packed[w * NSESS + s] = v;
        }
    }
}

// ---------------------------------------------------------------------------
// Kernel 2: filter. One warp = 32 sessions x one 128-trial chunk (+64 warmup).
// Warmup: scalar SEL steps (R3-proven math, verbatim).
// Output steps: 2-entry float4 coefficient LUT (validated by R4 error pattern).
// ---------------------------------------------------------------------------
#define OUT_ROW_F2 17
#define WARP_SMEM  (32 * OUT_ROW_F2)

__global__ void __launch_bounds__(128)
filter_kernel(const uint32_t* __restrict__ packed,
              const float* __restrict__ p_stay_raw,
              const float* __restrict__ c_raw,
              float* __restrict__ out) {
    __shared__ float2 stage[4 * WARP_SMEM];
    __shared__ float4 klut[2];   // per-step coefficients (K00,K01,K10,K11)

    const int lane  = threadIdx.x & 31;
    const int wid   = threadIdx.x >> 5;
    const int gwarp = blockIdx.x * 4 + wid;
    const int chunk = gwarp & (FNCHUNK - 1);
    const int sess0 = (gwarp >> 4) * 32;     // FNCHUNK == 16

    // model constants
    const float p  = 1.0f / (1.0f + __expf(-p_stay_raw[0]));
    const float c  = 1.0f / (1.0f + __expf(-c_raw[0]));
    const float A  = 0.5f * (1.0f + c);
    const float B  = 0.5f * (1.0f - c);
    const float q  = 0.5f * (1.0f + p);
    const float qm = 0.5f * (1.0f - p);
    // scalar-select constants for warmup (R3-proven path)
    const float k00_1 = q  * A, k00_0 = q  * B;
    const float k01_1 = qm * B, k01_0 = qm * A;
    const float k10_1 = qm * A, k10_0 = qm * B;
    const float k11_1 = q  * B, k11_0 = q  * A;

    if (threadIdx.x < 2) {
        float e0 = threadIdx.x ? A : B;
        float e1 = 1.0f - e0;
        klut[threadIdx.x] = make_float4(q * e0, qm * e1, qm * e0, q * e1);
    }
    __syncthreads();

    const int t_out0     = chunk * FCHUNK;
    const int t_start    = (chunk == 0) ? 0 : (t_out0 - FWARM);
    const int w_start    = t_start >> 5;
    const int warm_words = (t_out0 - t_start) >> 5;     // 0 or 2
    const int nwords     = warm_words + (FCHUNK >> 5);  // 4 or 6

    uint32_t wv[6];
#pragma unroll
    for (int k = 0; k < 6; k++)
        wv[k] = (k < nwords) ? packed[(w_start + k) * NSESS + sess0 + lane] : 0u;

    float2* ob = stage + wid * WARP_SMEM + lane * OUT_ROW_F2;
    float2* warp_stage = stage + wid * WARP_SMEM;

    float v0 = 0.5f, v1 = 0.5f;

    // ---- warmup: scalar SEL steps, renorm once per word (R3-proven) ----
    for (int k = 0; k < warm_words; k++) {
        const uint32_t w = wv[k];
#pragma unroll
        for (int i = 0; i < 32; i++) {
            const bool bit = (w >> i) & 1u;
            float K00 = bit ? k00_1 : k00_0;
            float K01 = bit ? k01_1 : k01_0;
            float K10 = bit ? k10_1 : k10_0;
            float K11 = bit ? k11_1 : k11_0;
            float m0 = K01 * v1;
            float m1 = K10 * v0;
            float a = fmaf(K00, v0, m0);
            float b = fmaf(K11, v1, m1);
            v0 = a; v1 = b;
        }
        float r = __frcp_rn(v0 + v1);
        v0 *= r; v1 *= r;
    }

    // ---- output words: klut steps, staged + coalesced flush per 16 trials ----
    for (int k = warm_words; k < nwords; k++) {
        const uint32_t w = wv[k];
#pragma unroll
        for (int h = 0; h < 2; h++) {
            float r_mid = 1.0f;
#pragma unroll
            for (int i = 0; i < 16; i++) {
                float4 K = klut[(w >> (h * 16 + i)) & 1u];
                float a = fmaf(K.x, v0, K.y * v1);
                float b = fmaf(K.z, v0, K.w * v1);
                float r = __frcp_rn(a + b);
                ob[i] = make_float2(a * r, b * r);
                if (i == 7) r_mid = r;
                v0 = a; v1 = b;
            }
            v0 *= r_mid; v1 *= r_mid;   // keep magnitudes bounded

            __syncwarp();
            const int t = t_start + k * 32 + h * 16;
            float2* og = (float2*)out + (long)sess0 * NTRIALS + t;
#pragma unroll
            for (int j = 0; j < 16; j++) {
                int row = 2 * j + (lane >> 4);
                int col = lane & 15;
                og[(long)row * NTRIALS + col] =
                    warp_stage[row * OUT_ROW_F2 + col];
            }
            __syncwarp();
        }
    }
}

extern "C" void kernel_launch(void* const* d_in, const int* in_sizes, int n_in,
                              void* d_out, int out_size) {
    const float* in   = (const float*)d_in[0];
    const float* praw = (const float*)d_in[1];
    const float* craw = (const float*)d_in[2];
    float* out = (float*)d_out;

    uint32_t* packed = nullptr;
    cudaGetSymbolAddress((void**)&packed, g_packed);

    pack_kernel<<<NSESS, 128>>>(in, packed);                                  // 4096 blocks
    filter_kernel<<<(NSESS / 32) * FNCHUNK / 4, 128>>>(packed, praw, craw, out); // 512 blocks
}